// round 4
// baseline (speedup 1.0000x reference)
#include <cuda_runtime.h>
#include <cuda_bf16.h>
#include <math.h>
#include <stdint.h>

#define T_TOK 2048
#define D     1024
#define DM    4096
#define E     8
#define CAP   2048

// ---------------- device scratch (static: allocation-guard safe) ----------------
__device__ int   g_cnt[E];
__device__ int   g_tok[E * CAP];
__device__ float g_wt [E * CAP];
__device__ __nv_bfloat16 g_xhi[T_TOK * D];
__device__ __nv_bfloat16 g_xlo[T_TOK * D];
__device__ __nv_bfloat16 g_hhi[(size_t)E * CAP * DM];   // 128 MB
__device__ __nv_bfloat16 g_hlo[(size_t)E * CAP * DM];   // 128 MB

// ---------------- helpers ----------------
__device__ __forceinline__ uint32_t smem_u32(const void* p) {
    uint32_t a;
    asm("{ .reg .u64 t; cvta.to.shared.u64 t, %1; cvt.u32.u64 %0, t; }" : "=r"(a) : "l"(p));
    return a;
}
__device__ __forceinline__ void split2(float v, __nv_bfloat16& h, __nv_bfloat16& l) {
    h = __float2bfloat16(v);
    l = __float2bfloat16(v - __bfloat162float(h));
}
__device__ __forceinline__ uint32_t packbf(__nv_bfloat16 a, __nv_bfloat16 b) {
    __nv_bfloat162 t = __halves2bfloat162(a, b);
    return *reinterpret_cast<uint32_t*>(&t);
}
__device__ __forceinline__ void cv8(float4 a, float4 b, uint4& uh, uint4& ul) {
    __nv_bfloat16 h0, l0, h1, l1, h2, l2, h3, l3;
    split2(a.x, h0, l0); split2(a.y, h1, l1); split2(a.z, h2, l2); split2(a.w, h3, l3);
    uh.x = packbf(h0, h1); uh.y = packbf(h2, h3);
    ul.x = packbf(l0, l1); ul.y = packbf(l2, l3);
    split2(b.x, h0, l0); split2(b.y, h1, l1); split2(b.z, h2, l2); split2(b.w, h3, l3);
    uh.z = packbf(h0, h1); uh.w = packbf(h2, h3);
    ul.z = packbf(l0, l1); ul.w = packbf(l2, l3);
}
__device__ __forceinline__ void ldsm4(uint32_t (&r)[4], uint32_t addr) {
    asm volatile("ldmatrix.sync.aligned.m8n8.x4.shared.b16 {%0,%1,%2,%3}, [%4];"
        : "=r"(r[0]), "=r"(r[1]), "=r"(r[2]), "=r"(r[3]) : "r"(addr));
}
__device__ __forceinline__ void ldsm4t(uint32_t (&r)[4], uint32_t addr) {
    asm volatile("ldmatrix.sync.aligned.m8n8.x4.trans.shared.b16 {%0,%1,%2,%3}, [%4];"
        : "=r"(r[0]), "=r"(r[1]), "=r"(r[2]), "=r"(r[3]) : "r"(addr));
}
__device__ __forceinline__ void mma16816(float* d, const uint32_t (&a)[4],
                                         uint32_t b0, uint32_t b1) {
    asm volatile(
        "mma.sync.aligned.m16n8k16.row.col.f32.bf16.bf16.f32 "
        "{%0,%1,%2,%3}, {%4,%5,%6,%7}, {%8,%9}, {%0,%1,%2,%3};"
        : "+f"(d[0]), "+f"(d[1]), "+f"(d[2]), "+f"(d[3])
        : "r"(a[0]), "r"(a[1]), "r"(a[2]), "r"(a[3]), "r"(b0), "r"(b1));
}
__device__ __forceinline__ void cpa16(uint32_t s, const void* g) {
    asm volatile("cp.async.cg.shared.global [%0], [%1], 16;" :: "r"(s), "l"(g));
}
#define CP_COMMIT() asm volatile("cp.async.commit_group;" ::: "memory")
#define CP_WAIT0()  asm volatile("cp.async.wait_group 0;" ::: "memory")

// ---------------------------------------------------------------
__global__ void zero_cnt_kernel() {
    if (threadIdx.x < E) g_cnt[threadIdx.x] = 0;
}

__global__ void convert_x_kernel(const float4* __restrict__ x4) {
    int i = blockIdx.x * blockDim.x + threadIdx.x;
    float4 v = x4[i];
    __nv_bfloat16 h0, h1, h2, h3, l0, l1, l2, l3;
    split2(v.x, h0, l0); split2(v.y, h1, l1);
    split2(v.z, h2, l2); split2(v.w, h3, l3);
    ((uint2*)g_xhi)[i] = make_uint2(packbf(h0, h1), packbf(h2, h3));
    ((uint2*)g_xlo)[i] = make_uint2(packbf(l0, l1), packbf(l2, l3));
}

__global__ void router_kernel(const float* __restrict__ x,
                              const float* __restrict__ Wg) {
    int t = blockIdx.x;
    int lane = threadIdx.x & 31;
    int w = threadIdx.x >> 5;
    const float* h = x + (size_t)t * D;
    float s = 0.f;
    for (int i = lane; i < D; i += 32) s += h[i] * Wg[i * E + w];
    #pragma unroll
    for (int o = 16; o; o >>= 1) s += __shfl_xor_sync(0xffffffffu, s, o);
    __shared__ float logits[E];
    if (lane == 0) logits[w] = s;
    __syncthreads();
    if (threadIdx.x == 0) {
        float m = -1e30f;
        #pragma unroll
        for (int e = 0; e < E; e++) m = fmaxf(m, logits[e]);
        float p[E];
        #pragma unroll
        for (int e = 0; e < E; e++) p[e] = expf(logits[e] - m);
        int e0 = 0;
        #pragma unroll
        for (int e = 1; e < E; e++) if (p[e] > p[e0]) e0 = e;
        int e1 = (e0 == 0) ? 1 : 0;
        #pragma unroll
        for (int e = 0; e < E; e++) { if (e == e0) continue; if (p[e] > p[e1]) e1 = e; }
        float rs = 1.f / (p[e0] + p[e1]);
        int i0 = atomicAdd(&g_cnt[e0], 1);
        g_tok[e0 * CAP + i0] = t;  g_wt[e0 * CAP + i0] = p[e0] * rs;
        int i1 = atomicAdd(&g_cnt[e1], 1);
        g_tok[e1 * CAP + i1] = t;  g_wt[e1 * CAP + i1] = p[e1] * rs;
    }
}

// ---------------------------------------------------------------
// Stage layouts (bytes):
//  up: Ah 0..10240, Al 10240..20480, Gh 20480, Gl 25088, Ih 29696, Il 34304  (38912)
//  dn: Ah 0..10240, Al 10240..20480, Bh 20480, Bl 25088                      (29696)
#define UP_STAGE 38912
#define DN_STAGE 29696
#define UP_SMEM  (2 * UP_STAGE)
#define DN_SMEM  (2 * DN_STAGE)

// Up-proj: hid = silu(X@Wg) * (X@Wi). Block 128(tok) x 64(n), BK=32, double-buffered.
__global__ void __launch_bounds__(256)
moe_up_kernel(const float* __restrict__ Wgate, const float* __restrict__ Win) {
    extern __shared__ char smem[];
    uint32_t sbase = smem_u32(smem);

    int e = blockIdx.z;
    int cnt = g_cnt[e];
    int row0 = blockIdx.x * 128;
    if (row0 >= cnt) return;
    int n0 = blockIdx.y * 64;

    int tid = threadIdx.x, wid = tid >> 5, lane = tid & 31;
    int warp_m = wid >> 1, warp_n = wid & 1;

    // A loader: 2 threads per row, each 2x16B chunks per stage
    int rA = tid >> 1;
    int q0 = (tid & 1) * 2;
    int tok = g_tok[e * CAP + min(row0 + rA, cnt - 1)];
    const char* gAh = (const char*)(g_xhi + (size_t)tok * D) + q0 * 16;
    const char* gAl = (const char*)(g_xlo + (size_t)tok * D) + q0 * 16;
    uint32_t sAoff = rA * 80 + q0 * 16;

    // B loader
    int bk = tid >> 3;
    int bn = (tid & 7) * 8;
    const float* pG = Wgate + (size_t)e * D * DM + (size_t)bk * DM + n0 + bn;
    const float* pI = Win   + (size_t)e * D * DM + (size_t)bk * DM + n0 + bn;
    uint32_t sBoff = 20480 + bk * 144 + bn * 2;

    // compute addresses (stage 0)
    uint32_t aH0 = sbase + (warp_m * 32 + (lane & 15)) * 80 + (lane >> 4) * 16;
    uint32_t bcol = (warp_n * 32 + (lane >> 4) * 8) * 2;
    uint32_t gH0 = sbase + 20480 + (lane & 15) * 144 + bcol;

    float aG[2][4][4], aI[2][4][4];
    #pragma unroll
    for (int i = 0; i < 2; i++)
        #pragma unroll
        for (int j = 0; j < 4; j++)
            #pragma unroll
            for (int k = 0; k < 4; k++) { aG[i][j][k] = 0.f; aI[i][j][k] = 0.f; }

    const int NIT = D / 32;
    float4 vg0, vg1, vi0, vi1;

    // ---- prologue: A(0) via cp.async, weights(0) to regs, STS B(0)
    {
        uint32_t dA = sbase + sAoff;
        cpa16(dA,          gAh);       cpa16(dA + 16,         gAh + 16);
        cpa16(dA + 10240,  gAl);       cpa16(dA + 10240 + 16, gAl + 16);
        CP_COMMIT();
        vg0 = *(const float4*)pG;  vg1 = *(const float4*)(pG + 4);
        vi0 = *(const float4*)pI;  vi1 = *(const float4*)(pI + 4);
        CP_WAIT0();
        uint4 uh, ul;
        cv8(vg0, vg1, uh, ul);
        *(uint4*)(smem + (sBoff - sbase + sbase) - sbase + sBoff - sBoff + (sBoff - 0)) = uh; // placeholder avoided below
    }
    // (direct STS without pointer gymnastics)
    {
        uint4 uh, ul;
        cv8(vg0, vg1, uh, ul);
        *(uint4*)(smem + (sBoff))        = uh;
        *(uint4*)(smem + (sBoff + 4608)) = ul;
        cv8(vi0, vi1, uh, ul);
        *(uint4*)(smem + (sBoff + 9216))  = uh;
        *(uint4*)(smem + (sBoff + 13824)) = ul;
    }

    for (int it = 0; it < NIT; ++it) {
        int p = it & 1;
        uint32_t ps = (uint32_t)p * UP_STAGE;
        uint32_t qs = (uint32_t)(1 - p) * UP_STAGE;
        __syncthreads();

        bool more = (it + 1 < NIT);
        if (more) {
            uint32_t dA = sbase + qs + sAoff;
            const char* ah = gAh + (size_t)(it + 1) * 64;
            const char* al = gAl + (size_t)(it + 1) * 64;
            cpa16(dA,          ah);      cpa16(dA + 16,         ah + 16);
            cpa16(dA + 10240,  al);      cpa16(dA + 10240 + 16, al + 16);
            const float* g  = pG + (size_t)(it + 1) * 32 * DM;
            const float* ii = pI + (size_t)(it + 1) * 32 * DM;
            vg0 = *(const float4*)g;   vg1 = *(const float4*)(g + 4);
            vi0 = *(const float4*)ii;  vi1 = *(const float4*)(ii + 4);
        }
        CP_COMMIT();

        // ---- compute on stage p
        uint32_t aH = aH0 + ps, aL = aH + 10240;
        uint32_t gH = gH0 + ps, gL = gH + 4608, iH = gH + 9216, iL = gH + 13824;
        #pragma unroll
        for (int kk = 0; kk < 32; kk += 16) {
            uint32_t A0h[4], A1h[4], A0l[4], A1l[4];
            ldsm4(A0h, aH + kk * 2);          ldsm4(A1h, aH + kk * 2 + 1280);
            ldsm4(A0l, aL + kk * 2);          ldsm4(A1l, aL + kk * 2 + 1280);
            #pragma unroll
            for (int jj = 0; jj < 2; jj++) {
                uint32_t bh[4], bl[4];
                ldsm4t(bh, gH + kk * 144 + jj * 32);
                ldsm4t(bl, gL + kk * 144 + jj * 32);
                mma16816(aG[0][2*jj],   A0h, bh[0], bh[1]);
                mma16816(aG[0][2*jj+1], A0h, bh[2], bh[3]);
                mma16816(aG[1][2*jj],   A1h, bh[0], bh[1]);
                mma16816(aG[1][2*jj+1], A1h, bh[2], bh[3]);
                mma16816(aG[0][2*jj],   A0h, bl[0], bl[1]);
                mma16816(aG[0][2*jj+1], A0h, bl[2], bl[3]);
                mma16816(aG[1][2*jj],   A1h, bl[0], bl[1]);
                mma16816(aG[1][2*jj+1], A1h, bl[2], bl[3]);
                mma16816(aG[0][2*jj],   A0l, bh[0], bh[1]);
                mma16816(aG[0][2*jj+1], A0l, bh[2], bh[3]);
                mma16816(aG[1][2*jj],   A1l, bh[0], bh[1]);
                mma16816(aG[1][2*jj+1], A1l, bh[2], bh[3]);

                ldsm4t(bh, iH + kk * 144 + jj * 32);
                ldsm4t(bl, iL + kk * 144 + jj * 32);
                mma16816(aI[0][2*jj],   A0h, bh[0], bh[1]);
                mma16816(aI[0][2*jj+1], A0h, bh[2], bh[3]);
                mma16816(aI[1][2*jj],   A1h, bh[0], bh[1]);
                mma16816(aI[1][2*jj+1], A1h, bh[2], bh[3]);
                mma16816(aI[0][2*jj],   A0h, bl[0], bl[1]);
                mma16816(aI[0][2*jj+1], A0h, bl[2], bl[3]);
                mma16816(aI[1][2*jj],   A1h, bl[0], bl[1]);
                mma16816(aI[1][2*jj+1], A1h, bl[2], bl[3]);
                mma16816(aI[0][2*jj],   A0l, bh[0], bh[1]);
                mma16816(aI[0][2*jj+1], A0l, bh[2], bh[3]);
                mma16816(aI[1][2*jj],   A1l, bh[0], bh[1]);
                mma16816(aI[1][2*jj+1], A1l, bh[2], bh[3]);
            }
        }

        if (more) {
            uint4 uh, ul;
            cv8(vg0, vg1, uh, ul);
            *(uint4*)(smem + qs + sBoff)         = uh;
            *(uint4*)(smem + qs + sBoff + 4608)  = ul;
            cv8(vi0, vi1, uh, ul);
            *(uint4*)(smem + qs + sBoff + 9216)  = uh;
            *(uint4*)(smem + qs + sBoff + 13824) = ul;
        }
        CP_WAIT0();
    }

    // epilogue: silu(g)*i -> split bf16 -> g_hhi/g_hlo
    int lr = warp_m * 32 + (lane >> 2);
    int cbase = n0 + warp_n * 32 + (lane & 3) * 2;
    #pragma unroll
    for (int i = 0; i < 2; i++) {
        #pragma unroll
        for (int h = 0; h < 2; h++) {
            int gr = row0 + lr + i * 16 + h * 8;
            if (gr >= cnt) continue;
            size_t base = (size_t)(e * CAP + gr) * DM;
            #pragma unroll
            for (int jn = 0; jn < 4; jn++) {
                float gg0 = aG[i][jn][2*h], gg1 = aG[i][jn][2*h+1];
                float ii0 = aI[i][jn][2*h], ii1 = aI[i][jn][2*h+1];
                float v0 = (gg0 / (1.f + expf(-gg0))) * ii0;
                float v1 = (gg1 / (1.f + expf(-gg1))) * ii1;
                __nv_bfloat16 h0, l0, h1, l1;
                split2(v0, h0, l0); split2(v1, h1, l1);
                *(uint32_t*)(g_hhi + base + cbase + jn * 8) = packbf(h0, h1);
                *(uint32_t*)(g_hlo + base + cbase + jn * 8) = packbf(l0, l1);
            }
        }
    }
}

// ---------------------------------------------------------------
// Down-proj + weighted scatter: out[tok] += w * (hid @ Wout). K = 4096.
__global__ void __launch_bounds__(256)
moe_dn_kernel(const float* __restrict__ Wout, float* __restrict__ out) {
    extern __shared__ char smem[];
    uint32_t sbase = smem_u32(smem);

    int e = blockIdx.z;
    int cnt = g_cnt[e];
    int row0 = blockIdx.x * 128;
    if (row0 >= cnt) return;
    int n0 = blockIdx.y * 64;

    int tid = threadIdx.x, wid = tid >> 5, lane = tid & 31;
    int warp_m = wid >> 1, warp_n = wid & 1;

    int rA = tid >> 1;
    int q0 = (tid & 1) * 2;
    int rowc = min(row0 + rA, cnt - 1);
    const char* gAh = (const char*)(g_hhi + (size_t)(e * CAP + rowc) * DM) + q0 * 16;
    const char* gAl = (const char*)(g_hlo + (size_t)(e * CAP + rowc) * DM) + q0 * 16;
    uint32_t sAoff = rA * 80 + q0 * 16;

    int bk = tid >> 3;
    int bn = (tid & 7) * 8;
    const float* pB = Wout + (size_t)e * DM * D + (size_t)bk * D + n0 + bn;
    uint32_t sBoff = 20480 + bk * 144 + bn * 2;

    uint32_t aH0 = sbase + (warp_m * 32 + (lane & 15)) * 80 + (lane >> 4) * 16;
    uint32_t bcol = (warp_n * 32 + (lane >> 4) * 8) * 2;
    uint32_t bH0 = sbase + 20480 + (lane & 15) * 144 + bcol;

    float acc[2][4][4];
    #pragma unroll
    for (int i = 0; i < 2; i++)
        #pragma unroll
        for (int j = 0; j < 4; j++)
            #pragma unroll
            for (int k = 0; k < 4; k++) acc[i][j][k] = 0.f;

    const int NIT = DM / 32;   // 128
    float4 vb0, vb1;

    {
        uint32_t dA = sbase + sAoff;
        cpa16(dA,          gAh);      cpa16(dA + 16,         gAh + 16);
        cpa16(dA + 10240,  gAl);      cpa16(dA + 10240 + 16, gAl + 16);
        CP_COMMIT();
        vb0 = *(const float4*)pB;  vb1 = *(const float4*)(pB + 4);
        CP_WAIT0();
        uint4 uh, ul;
        cv8(vb0, vb1, uh, ul);
        *(uint4*)(smem + sBoff)        = uh;
        *(uint4*)(smem + sBoff + 4608) = ul;
    }

    for (int it = 0; it < NIT; ++it) {
        int p = it & 1;
        uint32_t ps = (uint32_t)p * DN_STAGE;
        uint32_t qs = (uint32_t)(1 - p) * DN_STAGE;
        __syncthreads();

        bool more = (it + 1 < NIT);
        if (more) {
            uint32_t dA = sbase + qs + sAoff;
            const char* ah = gAh + (size_t)(it + 1) * 64;
            const char* al = gAl + (size_t)(it + 1) * 64;
            cpa16(dA,          ah);      cpa16(dA + 16,         ah + 16);
            cpa16(dA + 10240,  al);      cpa16(dA + 10240 + 16, al + 16);
            const float* w = pB + (size_t)(it + 1) * 32 * D;
            vb0 = *(const float4*)w;  vb1 = *(const float4*)(w + 4);
        }
        CP_COMMIT();

        uint32_t aH = aH0 + ps, aL = aH + 10240;
        uint32_t bH = bH0 + ps, bL = bH + 4608;
        #pragma unroll
        for (int kk = 0; kk < 32; kk += 16) {
            uint32_t A0h[4], A1h[4], A0l[4], A1l[4];
            ldsm4(A0h, aH + kk * 2);          ldsm4(A1h, aH + kk * 2 + 1280);
            ldsm4(A0l, aL + kk * 2);          ldsm4(A1l, aL + kk * 2 + 1280);
            #pragma unroll
            for (int jj = 0; jj < 2; jj++) {
                uint32_t bh[4], bl[4];
                ldsm4t(bh, bH + kk * 144 + jj * 32);
                ldsm4t(bl, bL + kk * 144 + jj * 32);
                mma16816(acc[0][2*jj],   A0h, bh[0], bh[1]);
                mma16816(acc[0][2*jj+1], A0h, bh[2], bh[3]);
                mma16816(acc[1][2*jj],   A1h, bh[0], bh[1]);
                mma16816(acc[1][2*jj+1], A1h, bh[2], bh[3]);
                mma16816(acc[0][2*jj],   A0h, bl[0], bl[1]);
                mma16816(acc[0][2*jj+1], A0h, bl[2], bl[3]);
                mma16816(acc[1][2*jj],   A1h, bl[0], bl[1]);
                mma16816(acc[1][2*jj+1], A1h, bl[2], bl[3]);
                mma16816(acc[0][2*jj],   A0l, bh[0], bh[1]);
                mma16816(acc[0][2*jj+1], A0l, bh[2], bh[3]);
                mma16816(acc[1][2*jj],   A1l, bh[0], bh[1]);
                mma16816(acc[1][2*jj+1], A1l, bh[2], bh[3]);
            }
        }

        if (more) {
            uint4 uh, ul;
            cv8(vb0, vb1, uh, ul);
            *(uint4*)(smem + qs + sBoff)        = uh;
            *(uint4*)(smem + qs + sBoff + 4608) = ul;
        }
        CP_WAIT0();
    }

    int lr = warp_m * 32 + (lane >> 2);
    int cbase = n0 + warp_n * 32 + (lane & 3) * 2;
    #pragma unroll
    for (int i = 0; i < 2; i++) {
        #pragma unroll
        for (int h = 0; h < 2; h++) {
            int gr = row0 + lr + i * 16 + h * 8;
            if (gr >= cnt) continue;
            int   tk = g_tok[e * CAP + gr];
            float wt = g_wt [e * CAP + gr];
            float* po = out + (size_t)tk * D;
            #pragma unroll
            for (int jn = 0; jn < 4; jn++) {
                atomicAdd(po + cbase + jn * 8,     acc[i][jn][2*h]     * wt);
                atomicAdd(po + cbase + jn * 8 + 1, acc[i][jn][2*h + 1] * wt);
            }
        }
    }
}

// ---------------------------------------------------------------
extern "C" void kernel_launch(void* const* d_in, const int* in_sizes, int n_in,
                              void* d_out, int out_size) {
    const float* x   = (const float*)d_in[0];
    const float* Wg  = (const float*)d_in[1];
    const float* Weg = (const float*)d_in[2];
    const float* Wei = (const float*)d_in[3];
    const float* Weo = (const float*)d_in[4];
    float* out = (float*)d_out;

    static int attr_set = 0;
    if (!attr_set) {
        cudaFuncSetAttribute(moe_up_kernel, cudaFuncAttributeMaxDynamicSharedMemorySize, UP_SMEM);
        cudaFuncSetAttribute(moe_dn_kernel, cudaFuncAttributeMaxDynamicSharedMemorySize, DN_SMEM);
        attr_set = 1;
    }

    cudaMemsetAsync(out, 0, (size_t)out_size * sizeof(float));
    zero_cnt_kernel<<<1, 32>>>();
    convert_x_kernel<<<(T_TOK * D / 4) / 256, 256>>>((const float4*)x);
    router_kernel<<<T_TOK, 256>>>(x, Wg);
    moe_up_kernel<<<dim3(CAP / 128, DM / 64, E), 256, UP_SMEM>>>(Weg, Wei);
    moe_dn_kernel<<<dim3(CAP / 128, D / 64, E), 256, DN_SMEM>>>(Weo, out);
}

// round 5
// speedup vs baseline: 1.2137x; 1.2137x over previous
#include <cuda_runtime.h>
#include <cuda_bf16.h>
#include <math.h>
#include <stdint.h>

#define T_TOK 2048
#define D     1024
#define DM    4096
#define E     8
#define CAP   2048

// ---------------- device scratch (static: allocation-guard safe) ----------------
__device__ int   g_cnt[E];
__device__ int   g_tok[E * CAP];
__device__ float g_wt [E * CAP];
__device__ __nv_bfloat16 g_xhi[T_TOK * D];
__device__ __nv_bfloat16 g_xlo[T_TOK * D];
__device__ __nv_bfloat16 g_hhi[(size_t)E * CAP * DM];
__device__ __nv_bfloat16 g_hlo[(size_t)E * CAP * DM];

// ---------------- helpers ----------------
__device__ __forceinline__ uint32_t smem_u32(const void* p) {
    uint32_t a;
    asm("{ .reg .u64 t; cvta.to.shared.u64 t, %1; cvt.u32.u64 %0, t; }" : "=r"(a) : "l"(p));
    return a;
}
__device__ __forceinline__ void split2(float v, __nv_bfloat16& h, __nv_bfloat16& l) {
    h = __float2bfloat16(v);
    l = __float2bfloat16(v - __bfloat162float(h));
}
__device__ __forceinline__ uint32_t packbf(__nv_bfloat16 a, __nv_bfloat16 b) {
    __nv_bfloat162 t = __halves2bfloat162(a, b);
    return *reinterpret_cast<uint32_t*>(&t);
}
__device__ __forceinline__ void cv8(float4 a, float4 b, uint4& uh, uint4& ul) {
    __nv_bfloat16 h0, l0, h1, l1, h2, l2, h3, l3;
    split2(a.x, h0, l0); split2(a.y, h1, l1); split2(a.z, h2, l2); split2(a.w, h3, l3);
    uh.x = packbf(h0, h1); uh.y = packbf(h2, h3);
    ul.x = packbf(l0, l1); ul.y = packbf(l2, l3);
    split2(b.x, h0, l0); split2(b.y, h1, l1); split2(b.z, h2, l2); split2(b.w, h3, l3);
    uh.z = packbf(h0, h1); uh.w = packbf(h2, h3);
    ul.z = packbf(l0, l1); ul.w = packbf(l2, l3);
}
__device__ __forceinline__ void ldsm4(uint32_t (&r)[4], uint32_t addr) {
    asm volatile("ldmatrix.sync.aligned.m8n8.x4.shared.b16 {%0,%1,%2,%3}, [%4];"
        : "=r"(r[0]), "=r"(r[1]), "=r"(r[2]), "=r"(r[3]) : "r"(addr));
}
__device__ __forceinline__ void ldsm4t(uint32_t (&r)[4], uint32_t addr) {
    asm volatile("ldmatrix.sync.aligned.m8n8.x4.trans.shared.b16 {%0,%1,%2,%3}, [%4];"
        : "=r"(r[0]), "=r"(r[1]), "=r"(r[2]), "=r"(r[3]) : "r"(addr));
}
__device__ __forceinline__ void mma16816(float* d, const uint32_t (&a)[4],
                                         uint32_t b0, uint32_t b1) {
    asm volatile(
        "mma.sync.aligned.m16n8k16.row.col.f32.bf16.bf16.f32 "
        "{%0,%1,%2,%3}, {%4,%5,%6,%7}, {%8,%9}, {%0,%1,%2,%3};"
        : "+f"(d[0]), "+f"(d[1]), "+f"(d[2]), "+f"(d[3])
        : "r"(a[0]), "r"(a[1]), "r"(a[2]), "r"(a[3]), "r"(b0), "r"(b1));
}
__device__ __forceinline__ void cpa16(uint32_t s, const void* g) {
    asm volatile("cp.async.cg.shared.global [%0], [%1], 16;" :: "r"(s), "l"(g));
}
#define CP_COMMIT() asm volatile("cp.async.commit_group;" ::: "memory")
#define CP_WAIT0()  asm volatile("cp.async.wait_group 0;" ::: "memory")

// stage layout (bytes), identical for both kernels:
//   A hi [0,10240)  A lo [10240,20480)  B region [20480, 20480+36864)
#define STAGE   57344
#define SMEMSZ  (2 * STAGE)

// ---------------------------------------------------------------
__global__ void zero_cnt_kernel() {
    if (threadIdx.x < E) g_cnt[threadIdx.x] = 0;
}

__global__ void convert_x_kernel(const float4* __restrict__ x4) {
    int i = blockIdx.x * blockDim.x + threadIdx.x;
    float4 v = x4[i];
    __nv_bfloat16 h0, h1, h2, h3, l0, l1, l2, l3;
    split2(v.x, h0, l0); split2(v.y, h1, l1);
    split2(v.z, h2, l2); split2(v.w, h3, l3);
    ((uint2*)g_xhi)[i] = make_uint2(packbf(h0, h1), packbf(h2, h3));
    ((uint2*)g_xlo)[i] = make_uint2(packbf(l0, l1), packbf(l2, l3));
}

__global__ void router_kernel(const float* __restrict__ x,
                              const float* __restrict__ Wg) {
    int t = blockIdx.x;
    int lane = threadIdx.x & 31;
    int w = threadIdx.x >> 5;
    const float* h = x + (size_t)t * D;
    float s = 0.f;
    for (int i = lane; i < D; i += 32) s += h[i] * Wg[i * E + w];
    #pragma unroll
    for (int o = 16; o; o >>= 1) s += __shfl_xor_sync(0xffffffffu, s, o);
    __shared__ float logits[E];
    if (lane == 0) logits[w] = s;
    __syncthreads();
    if (threadIdx.x == 0) {
        float m = -1e30f;
        #pragma unroll
        for (int e = 0; e < E; e++) m = fmaxf(m, logits[e]);
        float p[E];
        #pragma unroll
        for (int e = 0; e < E; e++) p[e] = expf(logits[e] - m);
        int e0 = 0;
        #pragma unroll
        for (int e = 1; e < E; e++) if (p[e] > p[e0]) e0 = e;
        int e1 = (e0 == 0) ? 1 : 0;
        #pragma unroll
        for (int e = 0; e < E; e++) { if (e == e0) continue; if (p[e] > p[e1]) e1 = e; }
        float rs = 1.f / (p[e0] + p[e1]);
        int i0 = atomicAdd(&g_cnt[e0], 1);
        g_tok[e0 * CAP + i0] = t;  g_wt[e0 * CAP + i0] = p[e0] * rs;
        int i1 = atomicAdd(&g_cnt[e1], 1);
        g_tok[e1 * CAP + i1] = t;  g_wt[e1 * CAP + i1] = p[e1] * rs;
    }
}

// ---------------------------------------------------------------
// Up-proj: M128 x N128 (G and I each), 8 warps, warp tile m64 x n32 (both mats).
__global__ void __launch_bounds__(256, 1)
moe_up_kernel(const float* __restrict__ Wgate, const float* __restrict__ Win) {
    extern __shared__ char smem[];
    uint32_t sb = smem_u32(smem);

    int e = blockIdx.z;
    int cnt = g_cnt[e];
    int row0 = blockIdx.x * 128;
    if (row0 >= cnt) return;
    int n0 = blockIdx.y * 128;

    int tid = threadIdx.x, wid = tid >> 5, lane = tid & 31;
    int warp_m = wid >> 2, warp_n = wid & 3;

    // A loader: row rA, chunks q0,q0+1 (16B each) per split
    int rA = tid >> 1, q0 = (tid & 1) * 2;
    int tok = g_tok[e * CAP + min(row0 + rA, cnt - 1)];
    const char* gAh = (const char*)(g_xhi + (size_t)tok * D) + q0 * 16;
    const char* gAl = (const char*)(g_xlo + (size_t)tok * D) + q0 * 16;
    uint32_t sA = rA * 80 + q0 * 16;

    // B loader
    int bk = tid >> 3, bn = (tid & 7) * 8;
    const float* pG = Wgate + (size_t)e * D * DM + (size_t)bk * DM + n0 + bn;
    const float* pI = Win   + (size_t)e * D * DM + (size_t)bk * DM + n0 + bn;
    uint32_t sB = 20480 + bk * 144 + bn * 2;

    // compute base addresses (relative; add stage offset ps)
    uint32_t aB = sb + (warp_m * 64 + (lane & 15)) * 80 + (lane >> 4) * 16;
    uint32_t bB = sb + 20480 + (warp_n >> 1) * 4608 + (lane & 15) * 144
                + ((warp_n & 1) * 32 + (lane >> 4) * 8) * 2;

    float acc[2][4][4][4];
    #pragma unroll
    for (int a = 0; a < 2; a++)
        #pragma unroll
        for (int b = 0; b < 4; b++)
            #pragma unroll
            for (int c = 0; c < 4; c++)
                #pragma unroll
                for (int d = 0; d < 4; d++) acc[a][b][c][d] = 0.f;

    const int NIT = D / 32;   // 32
    float4 vg[4], vi[4];

    #define LDW_UP(IT) do { \
        const float* _g = pG + (size_t)(IT) * 32 * DM; \
        const float* _i = pI + (size_t)(IT) * 32 * DM; \
        vg[0] = *(const float4*)_g;        vg[1] = *(const float4*)(_g + 4); \
        vg[2] = *(const float4*)(_g + 64); vg[3] = *(const float4*)(_g + 68); \
        vi[0] = *(const float4*)_i;        vi[1] = *(const float4*)(_i + 4); \
        vi[2] = *(const float4*)(_i + 64); vi[3] = *(const float4*)(_i + 68); \
    } while (0)

    #define STW_UP(ST) do { \
        uint4 uh, ul; \
        cv8(vg[0], vg[1], uh, ul); \
        *(uint4*)(smem + (ST) + sB)          = uh; \
        *(uint4*)(smem + (ST) + sB + 9216)   = ul; \
        cv8(vg[2], vg[3], uh, ul); \
        *(uint4*)(smem + (ST) + sB + 4608)   = uh; \
        *(uint4*)(smem + (ST) + sB + 13824)  = ul; \
        cv8(vi[0], vi[1], uh, ul); \
        *(uint4*)(smem + (ST) + sB + 18432)  = uh; \
        *(uint4*)(smem + (ST) + sB + 27648)  = ul; \
        cv8(vi[2], vi[3], uh, ul); \
        *(uint4*)(smem + (ST) + sB + 23040)  = uh; \
        *(uint4*)(smem + (ST) + sB + 32256)  = ul; \
    } while (0)

    #define CPA_T(ST, IT) do { \
        uint32_t _d = sb + (ST) + sA; \
        const char* _ah = gAh + (size_t)(IT) * 64; \
        const char* _al = gAl + (size_t)(IT) * 64; \
        cpa16(_d, _ah);          cpa16(_d + 16, _ah + 16); \
        cpa16(_d + 10240, _al);  cpa16(_d + 10240 + 16, _al + 16); \
    } while (0)

    // prologue
    LDW_UP(0); STW_UP(0); CPA_T(0, 0); CP_COMMIT();
    LDW_UP(1);
    CP_WAIT0();
    __syncthreads();

    for (int it = 0; it < NIT; ++it) {
        uint32_t ps = (uint32_t)(it & 1) * STAGE;
        uint32_t qs = STAGE - ps;
        bool m1 = (it + 1 < NIT);
        if (m1) { STW_UP(qs); CPA_T(qs, it + 1); }
        CP_COMMIT();
        if (it + 2 < NIT) LDW_UP(it + 2);

        #pragma unroll
        for (int kk = 0; kk < 2; kk++) {
            uint32_t Ah[4][4], Al[4][4];
            #pragma unroll
            for (int f = 0; f < 4; f++) {
                ldsm4(Ah[f], aB + ps + f * 1280 + kk * 32);
                ldsm4(Al[f], aB + ps + 10240 + f * 1280 + kk * 32);
            }
            #pragma unroll
            for (int mat = 0; mat < 2; mat++) {
                uint32_t sec = ps + mat * 18432 + kk * 2304;
                #pragma unroll
                for (int jt = 0; jt < 2; jt++) {
                    uint32_t bh[4], bl[4];
                    ldsm4t(bh, bB + sec + jt * 32);
                    ldsm4t(bl, bB + sec + 9216 + jt * 32);
                    #pragma unroll
                    for (int f = 0; f < 4; f++) {
                        mma16816(acc[mat][f][2*jt],   Ah[f], bh[0], bh[1]);
                        mma16816(acc[mat][f][2*jt+1], Ah[f], bh[2], bh[3]);
                        mma16816(acc[mat][f][2*jt],   Ah[f], bl[0], bl[1]);
                        mma16816(acc[mat][f][2*jt+1], Ah[f], bl[2], bl[3]);
                        mma16816(acc[mat][f][2*jt],   Al[f], bh[0], bh[1]);
                        mma16816(acc[mat][f][2*jt+1], Al[f], bh[2], bh[3]);
                    }
                }
            }
        }
        if (m1) CP_WAIT0();
        __syncthreads();
    }

    // epilogue: silu(G)*I -> split bf16 -> g_hhi/g_hlo
    #pragma unroll
    for (int f = 0; f < 4; f++) {
        #pragma unroll
        for (int h = 0; h < 2; h++) {
            int r = row0 + warp_m * 64 + f * 16 + (lane >> 2) + h * 8;
            if (r >= cnt) continue;
            size_t base = (size_t)(e * CAP + r) * DM;
            int col = n0 + warp_n * 32 + (lane & 3) * 2;
            #pragma unroll
            for (int n8 = 0; n8 < 4; n8++) {
                float g0 = acc[0][f][n8][2*h], g1 = acc[0][f][n8][2*h+1];
                float i0 = acc[1][f][n8][2*h], i1 = acc[1][f][n8][2*h+1];
                float v0 = g0 / (1.f + __expf(-g0)) * i0;
                float v1 = g1 / (1.f + __expf(-g1)) * i1;
                __nv_bfloat16 h0, l0, h1, l1;
                split2(v0, h0, l0); split2(v1, h1, l1);
                *(uint32_t*)(g_hhi + base + col + n8 * 8) = packbf(h0, h1);
                *(uint32_t*)(g_hlo + base + col + n8 * 8) = packbf(l0, l1);
            }
        }
    }
    #undef LDW_UP
    #undef STW_UP
}

// ---------------------------------------------------------------
// Down-proj + scatter: M128 x N256 tile, 8 warps, warp tile m64 x n64.
__global__ void __launch_bounds__(256, 1)
moe_dn_kernel(const float* __restrict__ Wout, float* __restrict__ out) {
    extern __shared__ char smem[];
    uint32_t sb = smem_u32(smem);

    int e = blockIdx.z;
    int cnt = g_cnt[e];
    int row0 = blockIdx.x * 128;
    if (row0 >= cnt) return;
    int n0 = blockIdx.y * 256;

    int tid = threadIdx.x, wid = tid >> 5, lane = tid & 31;
    int warp_m = wid >> 2, warp_n = wid & 3;

    int rA = tid >> 1, q0 = (tid & 1) * 2;
    int rowc = min(row0 + rA, cnt - 1);
    const char* gAh = (const char*)(g_hhi + (size_t)(e * CAP + rowc) * DM) + q0 * 16;
    const char* gAl = (const char*)(g_hlo + (size_t)(e * CAP + rowc) * DM) + q0 * 16;
    uint32_t sA = rA * 80 + q0 * 16;

    int bk = tid >> 3, bn = (tid & 7) * 8;
    const float* pB = Wout + (size_t)e * DM * D + (size_t)bk * D + n0 + bn;
    uint32_t sB = 20480 + bk * 144 + bn * 2;

    uint32_t aB = sb + (warp_m * 64 + (lane & 15)) * 80 + (lane >> 4) * 16;
    uint32_t bB = sb + 20480 + warp_n * 4608 + (lane & 15) * 144 + ((lane >> 4) * 8) * 2;

    float acc[4][8][4];
    #pragma unroll
    for (int a = 0; a < 4; a++)
        #pragma unroll
        for (int b = 0; b < 8; b++)
            #pragma unroll
            for (int c = 0; c < 4; c++) acc[a][b][c] = 0.f;

    const int NIT = DM / 32;   // 128
    float4 vb[8];

    #define LDW_DN(IT) do { \
        const float* _w = pB + (size_t)(IT) * 32 * D; \
        vb[0] = *(const float4*)_w;         vb[1] = *(const float4*)(_w + 4); \
        vb[2] = *(const float4*)(_w + 64);  vb[3] = *(const float4*)(_w + 68); \
        vb[4] = *(const float4*)(_w + 128); vb[5] = *(const float4*)(_w + 132); \
        vb[6] = *(const float4*)(_w + 192); vb[7] = *(const float4*)(_w + 196); \
    } while (0)

    #define STW_DN(ST) do { \
        uint4 uh, ul; \
        cv8(vb[0], vb[1], uh, ul); \
        *(uint4*)(smem + (ST) + sB)           = uh; \
        *(uint4*)(smem + (ST) + sB + 18432)   = ul; \
        cv8(vb[2], vb[3], uh, ul); \
        *(uint4*)(smem + (ST) + sB + 4608)    = uh; \
        *(uint4*)(smem + (ST) + sB + 23040)   = ul; \
        cv8(vb[4], vb[5], uh, ul); \
        *(uint4*)(smem + (ST) + sB + 9216)    = uh; \
        *(uint4*)(smem + (ST) + sB + 27648)   = ul; \
        cv8(vb[6], vb[7], uh, ul); \
        *(uint4*)(smem + (ST) + sB + 13824)   = uh; \
        *(uint4*)(smem + (ST) + sB + 32256)   = ul; \
    } while (0)

    #define CPA_T(ST, IT) do { \
        uint32_t _d = sb + (ST) + sA; \
        const char* _ah = gAh + (size_t)(IT) * 64; \
        const char* _al = gAl + (size_t)(IT) * 64; \
        cpa16(_d, _ah);          cpa16(_d + 16, _ah + 16); \
        cpa16(_d + 10240, _al);  cpa16(_d + 10240 + 16, _al + 16); \
    } while (0)

    LDW_DN(0); STW_DN(0); CPA_T(0, 0); CP_COMMIT();
    LDW_DN(1);
    CP_WAIT0();
    __syncthreads();

    for (int it = 0; it < NIT; ++it) {
        uint32_t ps = (uint32_t)(it & 1) * STAGE;
        uint32_t qs = STAGE - ps;
        bool m1 = (it + 1 < NIT);
        if (m1) { STW_DN(qs); CPA_T(qs, it + 1); }
        CP_COMMIT();
        if (it + 2 < NIT) LDW_DN(it + 2);

        #pragma unroll
        for (int kk = 0; kk < 2; kk++) {
            uint32_t Ah[4][4], Al[4][4];
            #pragma unroll
            for (int f = 0; f < 4; f++) {
                ldsm4(Ah[f], aB + ps + f * 1280 + kk * 32);
                ldsm4(Al[f], aB + ps + 10240 + f * 1280 + kk * 32);
            }
            #pragma unroll
            for (int jt = 0; jt < 4; jt++) {
                uint32_t bh[4], bl[4];
                ldsm4t(bh, bB + ps + kk * 2304 + jt * 32);
                ldsm4t(bl, bB + ps + 18432 + kk * 2304 + jt * 32);
                #pragma unroll
                for (int f = 0; f < 4; f++) {
                    mma16816(acc[f][2*jt],   Ah[f], bh[0], bh[1]);
                    mma16816(acc[f][2*jt+1], Ah[f], bh[2], bh[3]);
                    mma16816(acc[f][2*jt],   Ah[f], bl[0], bl[1]);
                    mma16816(acc[f][2*jt+1], Ah[f], bl[2], bl[3]);
                    mma16816(acc[f][2*jt],   Al[f], bh[0], bh[1]);
                    mma16816(acc[f][2*jt+1], Al[f], bh[2], bh[3]);
                }
            }
        }
        if (m1) CP_WAIT0();
        __syncthreads();
    }

    #pragma unroll
    for (int f = 0; f < 4; f++) {
        #pragma unroll
        for (int h = 0; h < 2; h++) {
            int r = row0 + warp_m * 64 + f * 16 + (lane >> 2) + h * 8;
            if (r >= cnt) continue;
            int   tk = g_tok[e * CAP + r];
            float wt = g_wt [e * CAP + r];
            float* po = out + (size_t)tk * D + n0 + warp_n * 64 + (lane & 3) * 2;
            #pragma unroll
            for (int n8 = 0; n8 < 8; n8++) {
                atomicAdd(po + n8 * 8,     acc[f][n8][2*h]     * wt);
                atomicAdd(po + n8 * 8 + 1, acc[f][n8][2*h + 1] * wt);
            }
        }
    }
}

// ---------------------------------------------------------------
extern "C" void kernel_launch(void* const* d_in, const int* in_sizes, int n_in,
                              void* d_out, int out_size) {
    const float* x   = (const float*)d_in[0];
    const float* Wg  = (const float*)d_in[1];
    const float* Weg = (const float*)d_in[2];
    const float* Wei = (const float*)d_in[3];
    const float* Weo = (const float*)d_in[4];
    float* out = (float*)d_out;

    static int attr_set = 0;
    if (!attr_set) {
        cudaFuncSetAttribute(moe_up_kernel, cudaFuncAttributeMaxDynamicSharedMemorySize, SMEMSZ);
        cudaFuncSetAttribute(moe_dn_kernel, cudaFuncAttributeMaxDynamicSharedMemorySize, SMEMSZ);
        attr_set = 1;
    }

    cudaMemsetAsync(out, 0, (size_t)out_size * sizeof(float));
    zero_cnt_kernel<<<1, 32>>>();
    convert_x_kernel<<<(T_TOK * D / 4) / 256, 256>>>((const float4*)x);
    router_kernel<<<T_TOK, 256>>>(x, Wg);
    moe_up_kernel<<<dim3(CAP / 128, DM / 128, E), 256, SMEMSZ>>>(Weg, Wei);
    moe_dn_kernel<<<dim3(CAP / 128, D / 256, E), 256, SMEMSZ>>>(Weo, out);
}